// round 6
// baseline (speedup 1.0000x reference)
#include <cuda_runtime.h>
#include <cuda_bf16.h>
#include <cstdint>

// Problem constants
#define NB 2048
#define NQ 128
#define NS 128   // K
#define NH 32    // N (hidden)
#define NC (NQ * NS)

// W smem stride in bf16 elems: 144 -> 288B rows. For LDS.64 B-fragment reads
// (h = lane>>2, byte off = h*288 + (lane&3)*8) the per-h bank offset is
// 72 words = 8 mod 32 -> each half-warp phase covers 32 distinct banks.
#define WSTRIDE 144

// ---- SMEM byte layout (W only; x goes gmem->registers) ----
#define OFF_W2   0                        // 32 f32
#define OFF_B1   128                      // 32 f32
#define OFF_WHI  256                      // 32*144*2 = 9216
#define OFF_WLO  (OFF_WHI + 9216)         // 9472
#define SMEM_TOTAL (OFF_WLO + 9216)       // 18688

__device__ __forceinline__ void mma16816(float* d, const uint32_t* a, uint32_t b0, uint32_t b1) {
    asm volatile(
        "mma.sync.aligned.m16n8k16.row.col.f32.bf16.bf16.f32 "
        "{%0,%1,%2,%3}, {%4,%5,%6,%7}, {%8,%9}, {%0,%1,%2,%3};"
        : "+f"(d[0]), "+f"(d[1]), "+f"(d[2]), "+f"(d[3])
        : "r"(a[0]), "r"(a[1]), "r"(a[2]), "r"(a[3]), "r"(b0), "r"(b1));
}

// fp32x2 -> (bf16x2 hi, bf16x2 lo) two-term split, packed for mma operands.
__device__ __forceinline__ void cvt_split(float2 v, uint32_t& hi, uint32_t& lo) {
    __nv_bfloat162 h2 = __float22bfloat162_rn(v);
    float2 hf = __bfloat1622float2(h2);
    float2 l;
    l.x = v.x - hf.x;
    l.y = v.y - hf.y;
    __nv_bfloat162 l2 = __float22bfloat162_rn(l);
    hi = *reinterpret_cast<uint32_t*>(&h2);
    lo = *reinterpret_cast<uint32_t*>(&l2);
}

__global__ void __launch_bounds__(128, 6)
div_enc_kernel(const float* __restrict__ x, const float* __restrict__ W1,
               const float* __restrict__ b1, const float* __restrict__ W2,
               const float* __restrict__ b2, float* __restrict__ out) {
    extern __shared__ char smem[];
    const int tid  = threadIdx.x;
    const int wid  = tid >> 5;
    const int lane = tid & 31;

    const int q     = blockIdx.x & (NQ - 1);
    const int btile = blockIdx.x >> 7;

    // ---- stage W2 / b1 ----
    if (tid < 32) {
        ((float*)(smem + OFF_W2))[tid] = W2[q * NH + tid];
        ((float*)(smem + OFF_B1))[tid] = b1[q * NH + tid];
    }

    // ---- W1[q] (gmem [s][h]) -> smem Bt[h][s] K-major (natural s order), hi/lo ----
    {
        const float* w1q = W1 + (size_t)q * NS * NH;
        const int h  = tid & 31;
        const int sb = tid >> 5;
        __nv_bfloat16* whi = (__nv_bfloat16*)(smem + OFF_WHI);
        __nv_bfloat16* wlo = (__nv_bfloat16*)(smem + OFF_WLO);
#pragma unroll 8
        for (int j = 0; j < 32; j++) {
            const int s = j * 4 + sb;
            float v = w1q[s * NH + h];               // coalesced: h contiguous
            __nv_bfloat16 hi = __float2bfloat16(v);
            __nv_bfloat16 lo = __float2bfloat16(v - __bfloat162float(hi));
            whi[h * WSTRIDE + s] = hi;
            wlo[h * WSTRIDE + s] = lo;
        }
    }
    __syncthreads();

    // ---- mainloop ----
    // k-slot permutation: thread F=lane&3 loads float4 at global cols 4F..4F+3.
    //   MMA slot-pair (2F,2F+1)   := global col pair (4F,4F+1)   -> frag a0/a1, b word .x
    //   MMA slot-pair (2F+8,2F+9) := global col pair (4F+2,4F+3) -> frag a2/a3, b word .y
    // B smem keeps natural s-order, so one LDS.64 at col 4F yields both b words.
    float acc[2][4][4];
#pragma unroll
    for (int mt = 0; mt < 2; mt++)
#pragma unroll
        for (int nt = 0; nt < 4; nt++)
#pragma unroll
            for (int i = 0; i < 4; i++) acc[mt][nt][i] = 0.f;

    // A load base: row0 = btile*128 + wid*32 + (lane>>2), col = q*NS + (lane&3)*4
    const float* xb = x + (size_t)(btile * 128 + wid * 32 + (lane >> 2)) * NC
                        + (size_t)q * NS + (size_t)((lane & 3) * 4);

    const char* bHiBase = smem + OFF_WHI + ((lane >> 2) * WSTRIDE + (lane & 3) * 4) * 2;
    const char* bLoBase = smem + OFF_WLO + ((lane >> 2) * WSTRIDE + (lane & 3) * 4) * 2;

    // preload kstep 0: 4 x LDG.128 (mt x rowhalf)
    float4 v[2][2];
#pragma unroll
    for (int mt = 0; mt < 2; mt++)
#pragma unroll
        for (int rh = 0; rh < 2; rh++)
            v[mt][rh] = __ldcs((const float4*)(xb + mt * 16 * NC + rh * 8 * NC));

#pragma unroll
    for (int ks = 0; ks < 8; ks++) {
        // convert current kstep into fragments
        uint32_t aHi[2][4], aLo[2][4];
#pragma unroll
        for (int mt = 0; mt < 2; mt++)
#pragma unroll
            for (int rh = 0; rh < 2; rh++) {
                float2 p0 = make_float2(v[mt][rh].x, v[mt][rh].y);
                float2 p1 = make_float2(v[mt][rh].z, v[mt][rh].w);
                cvt_split(p0, aHi[mt][rh],     aLo[mt][rh]);      // a0/a1
                cvt_split(p1, aHi[mt][2 + rh], aLo[mt][2 + rh]);  // a2/a3
            }

        // prefetch next kstep's loads before the MMA block
        if (ks < 7) {
#pragma unroll
            for (int mt = 0; mt < 2; mt++)
#pragma unroll
                for (int rh = 0; rh < 2; rh++)
                    v[mt][rh] = __ldcs((const float4*)(xb + mt * 16 * NC + rh * 8 * NC
                                                          + (ks + 1) * 16));
        }

        const uint32_t kb = (uint32_t)ks * 32u;   // 16 bf16 = 32 bytes
#pragma unroll
        for (int nt = 0; nt < 4; nt++) {
            const uint32_t noff = (uint32_t)(nt * 8 * WSTRIDE) * 2u + kb;
            const uint2 bh = *(const uint2*)(bHiBase + noff);   // LDS.64
            const uint2 bl = *(const uint2*)(bLoBase + noff);   // LDS.64
            mma16816(acc[0][nt], aHi[0], bh.x, bh.y);
            mma16816(acc[1][nt], aHi[1], bh.x, bh.y);
            mma16816(acc[0][nt], aHi[0], bl.x, bl.y);
            mma16816(acc[1][nt], aHi[1], bl.x, bl.y);
            mma16816(acc[0][nt], aLo[0], bh.x, bh.y);
            mma16816(acc[1][nt], aLo[1], bh.x, bh.y);
        }
    }

    // ---- epilogue: +b1, ELU, dot W2, quad-reduce, store ----
    float b1v[4][2], w2v[4][2];
    const float* s_b1 = (const float*)(smem + OFF_B1);
    const float* s_w2 = (const float*)(smem + OFF_W2);
#pragma unroll
    for (int nt = 0; nt < 4; nt++)
#pragma unroll
        for (int i = 0; i < 2; i++) {
            const int h = nt * 8 + (lane & 3) * 2 + i;
            b1v[nt][i] = s_b1[h];
            w2v[nt][i] = s_w2[h];
        }
    const float b2q = b2[q];

#pragma unroll
    for (int mt = 0; mt < 2; mt++) {
        float p0 = 0.f, p1 = 0.f;
#pragma unroll
        for (int nt = 0; nt < 4; nt++) {
#pragma unroll
            for (int i = 0; i < 2; i++) {
                float hv = acc[mt][nt][i] + b1v[nt][i];
                float e  = (hv > 0.f) ? hv : (__expf(hv) - 1.0f);
                p0 = fmaf(e, w2v[nt][i], p0);
                hv = acc[mt][nt][2 + i] + b1v[nt][i];
                e  = (hv > 0.f) ? hv : (__expf(hv) - 1.0f);
                p1 = fmaf(e, w2v[nt][i], p1);
            }
        }
        p0 += __shfl_xor_sync(0xFFFFFFFFu, p0, 1);
        p0 += __shfl_xor_sync(0xFFFFFFFFu, p0, 2);
        p1 += __shfl_xor_sync(0xFFFFFFFFu, p1, 1);
        p1 += __shfl_xor_sync(0xFFFFFFFFu, p1, 2);
        if ((lane & 3) == 0) {
            const int m = btile * 128 + wid * 32 + mt * 16 + (lane >> 2);
            out[(size_t)m * NQ + q]       = p0 + b2q;
            out[(size_t)(m + 8) * NQ + q] = p1 + b2q;
        }
    }
}

extern "C" void kernel_launch(void* const* d_in, const int* in_sizes, int n_in,
                              void* d_out, int out_size) {
    const float* x  = (const float*)d_in[0];
    const float* W1 = (const float*)d_in[1];
    const float* b1 = (const float*)d_in[2];
    const float* W2 = (const float*)d_in[3];
    const float* b2 = (const float*)d_in[4];
    float* out = (float*)d_out;

    cudaFuncSetAttribute(div_enc_kernel, cudaFuncAttributeMaxDynamicSharedMemorySize, SMEM_TOTAL);
    div_enc_kernel<<<(NB / 128) * NQ, 128, SMEM_TOTAL>>>(x, W1, b1, W2, b2, out);
}